// round 14
// baseline (speedup 1.0000x reference)
#include <cuda_runtime.h>
#include <math.h>

typedef unsigned long long ull;

#define FEAT_DIM 360
#define MAXB     32
#define NT       384
#define TW       64          // tile width (output)
#define TH       32          // tile height (output)

__device__ float g_feat[MAXB * FEAT_DIM];

// ---------------- packed f32x2 helpers ----------------
__device__ __forceinline__ ull pack2(float lo, float hi) {
    ull r; asm("mov.b64 %0, {%1, %2};" : "=l"(r) : "f"(lo), "f"(hi)); return r;
}
__device__ __forceinline__ ull fma2(ull a, ull b, ull c) {
    ull r; asm("fma.rn.f32x2 %0, %1, %2, %3;" : "=l"(r) : "l"(a), "l"(b), "l"(c)); return r;
}
__device__ __forceinline__ ull mul2(ull a, ull b) {
    ull r; asm("mul.rn.f32x2 %0, %1, %2;" : "=l"(r) : "l"(a), "l"(b)); return r;
}
__device__ __forceinline__ ull add2(ull a, ull b) {
    ull r; asm("add.rn.f32x2 %0, %1, %2;" : "=l"(r) : "l"(a), "l"(b)); return r;
}
// (hi(a), lo(b)) -- exactly 2 register moves
__device__ __forceinline__ ull mid2(ull a, ull b) {
    ull r;
    asm("{\n\t"
        ".reg .b32 al, ah, bl, bh;\n\t"
        "mov.b64 {al, ah}, %1;\n\t"
        "mov.b64 {bl, bh}, %2;\n\t"
        "mov.b64 %0, {ah, bl};\n\t"
        "}" : "=l"(r) : "l"(a), "l"(b));
    return r;
}

#define C06P 0x3F19999A3F19999AULL
#define C04P 0x3ECCCCCD3ECCCCCDULL
#define ONE2 0x3F8000003F800000ULL

// lrelu(v) = 0.6*v + 0.4*|v|  (exact), branch-free packed
__device__ __forceinline__ ull lrelu2(ull v) {
    ull a = v & 0x7FFFFFFF7FFFFFFFULL;
    return fma2(a, (ull)C04P, mul2(v, (ull)C06P));
}

// ---------------- merged preamble: mean(thumb) + GEMV ----------------
#define FT 384
__global__ void feat_kernel(const float* __restrict__ thumb,
                            const float* __restrict__ Wm,
                            const float* __restrict__ bm, int HW) {
    int b = blockIdx.x;
    int tid = threadIdx.x;
    __shared__ float red[FT / 32][3];
    __shared__ float m[3];
    const float4* p = (const float4*)(thumb + (size_t)b * 3 * HW);
    int n4c = HW / 4;
    float s[3];
    #pragma unroll
    for (int c = 0; c < 3; c++) {
        float acc = 0.0f;
        for (int i = tid; i < n4c; i += FT) {
            float4 v = p[c * n4c + i];
            acc += (v.x + v.y) + (v.z + v.w);
        }
        s[c] = acc;
    }
    #pragma unroll
    for (int c = 0; c < 3; c++) {
        float v = s[c];
        #pragma unroll
        for (int o = 16; o > 0; o >>= 1) v += __shfl_down_sync(0xffffffffu, v, o);
        if ((tid & 31) == 0) red[tid >> 5][c] = v;
    }
    __syncthreads();
    if (tid == 0) {
        float inv = 1.0f / (float)HW;
        #pragma unroll
        for (int c = 0; c < 3; c++) {
            float t = 0.0f;
            #pragma unroll
            for (int w = 0; w < FT / 32; w++) t += red[w][c];
            m[c] = t * inv;
        }
    }
    __syncthreads();
    if (tid < FEAT_DIM) {
        g_feat[b * FEAT_DIM + tid] =
            m[0] * Wm[tid] + m[1] * Wm[FEAT_DIM + tid] + m[2] * Wm[2 * FEAT_DIM + tid]
            + bm[tid];
    }
}

// ---------------- one 3x3 conv layer on pixel pairs (rectangular frames) ----------------
// src frame: SW x SH x 3; dst frame: (SW-2) x (SH-2) x 3.
// v0/v2 direct 64-bit LDS; v1 via 2-MOV mid2. Scalar weight staging (R10-proven).
template <int SW, int SH, int SLOTS, bool STORE>
__device__ __forceinline__ void conv3_pairs(const float* __restrict__ src,
                                            float* __restrict__ dst,
                                            const ull* __restrict__ wPack,
                                            int tid, ull outReg[][3]) {
    constexpr int DW = SW - 2, DH = SH - 2;
    constexpr int PW = DW / 2;
    constexpr int NP = DH * PW;
    constexpr int CH_S = SW * SH;
    constexpr int CH_D = DW * DH;
    int off[SLOTS];
    #pragma unroll
    for (int k = 0; k < SLOTS; k++) {
        int p = tid + k * NT;
        int y = p / PW, x = (p - y * PW) * 2;
        off[k] = y * SW + x;
    }
    ull acc[SLOTS][3];
    #pragma unroll
    for (int oc = 0; oc < 3; oc++) {
        ull bb = wPack[81 + oc];
        #pragma unroll
        for (int k = 0; k < SLOTS; k++) acc[k][oc] = bb;
    }
    #pragma unroll
    for (int ic = 0; ic < 3; ic++) {
        #pragma unroll
        for (int ky = 0; ky < 3; ky++) {
            ull w00 = wPack[ 0 + ic * 9 + ky * 3 + 0];
            ull w01 = wPack[ 0 + ic * 9 + ky * 3 + 1];
            ull w02 = wPack[ 0 + ic * 9 + ky * 3 + 2];
            ull w10 = wPack[27 + ic * 9 + ky * 3 + 0];
            ull w11 = wPack[27 + ic * 9 + ky * 3 + 1];
            ull w12 = wPack[27 + ic * 9 + ky * 3 + 2];
            ull w20 = wPack[54 + ic * 9 + ky * 3 + 0];
            ull w21 = wPack[54 + ic * 9 + ky * 3 + 1];
            ull w22 = wPack[54 + ic * 9 + ky * 3 + 2];
            #pragma unroll
            for (int k = 0; k < SLOTS; k++) {
                bool active = ((k + 1) * NT <= NP) || (tid + k * NT < NP);
                if (active) {
                    const float* s = src + ic * CH_S + ky * SW + off[k];
                    ull v0 = *(const ull*)s;
                    ull v2 = *(const ull*)(s + 2);
                    ull v1 = mid2(v0, v2);
                    acc[k][0] = fma2(w00, v0, acc[k][0]);
                    acc[k][1] = fma2(w10, v0, acc[k][1]);
                    acc[k][2] = fma2(w20, v0, acc[k][2]);
                    acc[k][0] = fma2(w01, v1, acc[k][0]);
                    acc[k][1] = fma2(w11, v1, acc[k][1]);
                    acc[k][2] = fma2(w21, v1, acc[k][2]);
                    acc[k][0] = fma2(w02, v2, acc[k][0]);
                    acc[k][1] = fma2(w12, v2, acc[k][1]);
                    acc[k][2] = fma2(w22, v2, acc[k][2]);
                }
            }
        }
    }
    #pragma unroll
    for (int k = 0; k < SLOTS; k++) {
        int p = tid + k * NT;
        bool active = ((k + 1) * NT <= NP) || (p < NP);
        if (active) {
            int y = p / PW, x = (p - y * PW) * 2;
            #pragma unroll
            for (int oc = 0; oc < 3; oc++) {
                ull r = lrelu2(acc[k][oc]);
                if (STORE) *(ull*)(dst + oc * CH_D + y * DW + x) = r;
                else       outReg[k][oc] = r;
            }
        }
    }
}

// frame geometry
#define AW 70
#define AH 38
#define CHA (AW * AH)          // 2660
#define CHB (68 * 36)          // 2448
#define CHC (66 * 34)          // 2244
// dynamic smem: sPack (360 ull) | bufA | bufB | bufC
#define SMEM_BYTES (360 * 8 + (CHA + CHB + CHC) * 3 * 4)   // 91,104

// ---------------- fused conv stack + attention ----------------
__global__ __launch_bounds__(NT, 2) void conv_att_kernel(
    const float* __restrict__ xMain, const float* __restrict__ xThumb,
    float* __restrict__ outAll, int Hm, int B, int tilesX, int tilesY) {
    extern __shared__ __align__(16) ull pool[];
    ull*   sPack = pool;
    float* bufA  = (float*)(pool + 360);
    float* bufB  = bufA + 3 * CHA;
    float* bufC  = bufB + 3 * CHB;

    int mainTotal = B * tilesX * tilesY;
    int bid = blockIdx.x;
    const float* src; float* dst;
    int H, b, y0, x0;
    if (bid < mainTotal) {
        int per = tilesX * tilesY;
        b = bid / per;
        int t = bid - b * per;
        int ty = t / tilesX, tx = t - ty * tilesX;
        H = Hm; y0 = ty * TH; x0 = tx * TW;
        src = xMain + (size_t)b * 3 * H * H;
        dst = outAll + (size_t)b * 3 * H * H;
    } else {
        int r = bid - mainTotal;
        b = r >> 1;
        int t = r & 1;                  // thumb: 1 x-tile, 2 y-tiles
        H = 64; y0 = t * TH; x0 = 0;
        src = xThumb + (size_t)b * 3 * 64 * 64;
        dst = outAll + (size_t)B * 3 * Hm * Hm + (size_t)b * 3 * 64 * 64;
    }
    int tid = threadIdx.x;

    // load input tile with halo 3 (zero-padded) -- overlaps feat kernel (PDL)
    for (int i = tid; i < 3 * CHA; i += NT) {
        int c = i / CHA;
        int r = i - c * CHA;
        int y = r / AW, xx = r - y * AW;
        int gy = y0 - 3 + y, gx = x0 - 3 + xx;
        float v = 0.0f;
        if (gy >= 0 && gy < H && gx >= 0 && gx < H)
            v = __ldg(&src[((size_t)c * H + gy) * H + gx]);
        bufA[i] = v;
    }

    // wait for feat_kernel's g_feat writes, then splat features
    cudaGridDependencySynchronize();
    for (int j = tid; j < FEAT_DIM; j += NT) {
        float f = g_feat[b * FEAT_DIM + j];
        sPack[j] = pack2(f, f);
    }
    __syncthreads();

    // L1: bufA(70x38) -> bufB(68x36)   [1224 pairs -> 4 slots]
    conv3_pairs<AW, AH, 4, true>(bufA, bufB, sPack, tid, (ull(*)[3])nullptr);
    __syncthreads();

    // L2: bufB(68x36) -> bufC(66x34)   [1122 pairs -> 3 slots]  (bufA intact)
    conv3_pairs<68, 36, 3, true>(bufB, bufC, sPack + 84, tid, (ull(*)[3])nullptr);
    __syncthreads();

    // L3: bufC(66x34) -> registers     [1024 pairs -> 3 slots]
    ull cur[3][3];
    conv3_pairs<66, 34, 3, false>(bufC, (float*)nullptr, sPack + 168, tid, cur);

    // 5x conv1x1 + residual + attention + store (per active slot)
    float invH = 1.0f / (float)H;
    #pragma unroll
    for (int k = 0; k < 3; k++) {
        int p = tid + k * NT;
        if (p < 1024) {
            ull c0 = cur[k][0], c1 = cur[k][1], c2 = cur[k][2];
            #pragma unroll
            for (int l = 0; l < 5; l++) {
                const ull* wl = sPack + 252 + l * 12;
                ull n0 = fma2(wl[0], c0, fma2(wl[1], c1, fma2(wl[2], c2, wl[9])));
                ull n1 = fma2(wl[3], c0, fma2(wl[4], c1, fma2(wl[5], c2, wl[10])));
                ull n2 = fma2(wl[6], c0, fma2(wl[7], c1, fma2(wl[8], c2, wl[11])));
                c0 = lrelu2(n0); c1 = lrelu2(n1); c2 = lrelu2(n2);
            }
            ull vv[3] = {c0, c1, c2};
            int y = p >> 5, x = (p & 31) * 2;
            int gy = y0 + y, gx = x0 + x;
            float hv = (float)gy * invH;
            ull hP = pack2(hv, hv);
            ull wP = pack2((float)gx * invH, (float)(gx + 1) * invH);
            #pragma unroll
            for (int oc = 0; oc < 3; oc++) {
                // residual from intact input tile (center offset +3,+3)
                const float* q = &bufA[(oc * AH + 3 + y) * AW + 2 + x];
                ull e0 = *(const ull*)q;
                ull e1 = *(const ull*)(q + 2);
                ull v = add2(mid2(e0, e1), vv[oc]);
                ull att = (ull)ONE2;
                #pragma unroll
                for (int i = 0; i < 4; i++) {
                    const ull* f = sPack + 312 + oc * 16 + i * 4;
                    ull t = fma2(f[0], hP, fma2(f[1], wP, fma2(f[2], v, f[3])));
                    att = mul2(att, t);
                }
                ull r = mul2(v, add2((ull)ONE2, att));
                *(ull*)&dst[((size_t)oc * H + gy) * H + gx] = r;
            }
        }
    }
}

// ---------------- launch ----------------
extern "C" void kernel_launch(void* const* d_in, const int* in_sizes, int n_in,
                              void* d_out, int out_size) {
    const float* x     = (const float*)d_in[0];
    const float* thumb = (const float*)d_in[1];
    const float* Wm    = (const float*)d_in[2];
    const float* bm    = (const float*)d_in[3];
    float* out = (float*)d_out;

    int Ht = 64;
    int B  = in_sizes[1] / (3 * Ht * Ht);
    if (B < 1) B = 1;
    if (B > MAXB) B = MAXB;
    int hw = in_sizes[0] / (3 * B);
    int Hm = (int)(sqrt((double)hw) + 0.5);

    cudaFuncSetAttribute(conv_att_kernel,
                         cudaFuncAttributeMaxDynamicSharedMemorySize, SMEM_BYTES);

    feat_kernel<<<B, FT>>>(thumb, Wm, bm, Ht * Ht);

    int tilesX = Hm / TW, tilesY = Hm / TH;
    int total = B * tilesX * tilesY + B * 2;   // main tiles + thumb (1x2 tiles each)

    cudaLaunchConfig_t cfg = {};
    cfg.gridDim = dim3(total);
    cfg.blockDim = dim3(NT);
    cfg.dynamicSmemBytes = SMEM_BYTES;
    cfg.stream = 0;
    cudaLaunchAttribute attrs[1];
    attrs[0].id = cudaLaunchAttributeProgrammaticStreamSerialization;
    attrs[0].val.programmaticStreamSerializationAllowed = 1;
    cfg.attrs = attrs;
    cfg.numAttrs = 1;
    cudaLaunchKernelEx(&cfg, conv_att_kernel, x, thumb, out, Hm, B, tilesX, tilesY);
}